// round 4
// baseline (speedup 1.0000x reference)
#include <cuda_runtime.h>

#define BSZ 8
#define CDIM 64
#define HDIM 128
#define WDIM 128
#define HID 128

// ---- scratch (device globals; allocation-free) ----
__device__ float g_xp[BSZ*HDIM*WDIM*HID];   // x_proj [b][h][w][o]
__device__ float g_hs[BSZ*HDIM*WDIM*HID];   // h_hor -> h_sum, same layout
__device__ float g_WinT[64*128];            // [k=c][o]
__device__ float g_WoutT[128*64];           // [o][c]
__device__ float g_At[128];                 // tanh(A)

typedef unsigned long long u64;

// ---- packed f32x2 (FFMA2) helpers ----
__device__ __forceinline__ u64 pack2(float lo, float hi) {
    u64 r;
    asm("mov.b64 %0, {%1, %2};" : "=l"(r)
        : "r"(__float_as_uint(lo)), "r"(__float_as_uint(hi)));
    return r;
}
__device__ __forceinline__ float2 unpack2(u64 v) {
    unsigned int a, b;
    asm("mov.b64 {%0, %1}, %2;" : "=r"(a), "=r"(b) : "l"(v));
    return make_float2(__uint_as_float(a), __uint_as_float(b));
}
__device__ __forceinline__ void ffma2(u64& d, u64 a, u64 b) {
    asm("fma.rn.f32x2 %0, %1, %2, %0;" : "+l"(d) : "l"(a), "l"(b));
}
__device__ __forceinline__ u64 add2(u64 a, u64 b) {
    u64 r;
    asm("add.rn.f32x2 %0, %1, %2;" : "=l"(r) : "l"(a), "l"(b));
    return r;
}

// ---- bilinear prior 32->128, align_corners, clip ----
__device__ __forceinline__ float prior_at(const float* __restrict__ prior,
                                          int b, int h, int w) {
    const float s = 31.0f / 127.0f;
    float ys = h * s, xs = w * s;
    int y0 = (int)ys, x0 = (int)xs;
    int y1 = min(y0 + 1, 31), x1 = min(x0 + 1, 31);
    float wy = ys - (float)y0, wx = xs - (float)x0;
    const float* p = prior + b * 1024;
    float p00 = p[y0*32+x0], p01 = p[y0*32+x1];
    float p10 = p[y1*32+x0], p11 = p[y1*32+x1];
    float top = p00 + (p01 - p00) * wx;
    float bot = p10 + (p11 - p10) * wx;
    float v = top + (bot - top) * wy;
    return fminf(1.0f, fmaxf(-1.0f, v));
}

// ---- K0: weight transposes + tanh(A) ----
__global__ void k_setup(const float* __restrict__ Win,
                        const float* __restrict__ Wout,
                        const float* __restrict__ A) {
    int i = blockIdx.x * 256 + threadIdx.x;
    if (i < 64 * 128) {
        int o = i & 127, k = i >> 7;
        g_WinT[i] = Win[o * 64 + k];
        int oo = i >> 6, c = i & 63;
        g_WoutT[i] = Wout[c * 128 + oo];
    }
    if (i < 128) g_At[i] = tanhf(A[i]);
}

// ---- K1: per-(b,h) row: GEMM1 (C=64 -> HID=128) + bias, h-scan ----
// grid(128,8), 256 thr, 64KB dyn smem.
__global__ __launch_bounds__(256) void k_proj_hscan(
    const float* __restrict__ x, const float* __restrict__ prior,
    const float* __restrict__ b_in, const float* __restrict__ Bvec,
    const float* __restrict__ alpha_p)
{
    extern __shared__ float smem[];
    float* s_W = smem;          // [k*128 + o]   32KB
    float* s_F = smem + 8192;   // [k*128 + w]   32KB
    float* s_P = smem;          // [w*128 + o]   64KB (reuse)
    __shared__ float s_pr[128];

    const int t = threadIdx.x;
    const int h = blockIdx.x, b = blockIdx.y;
    const float alpha = __ldg(alpha_p);

    if (t < 128) s_pr[t] = prior_at(prior, b, h, t);
    __syncthreads();

    const float* xrow = x + (long)b * 1048576 + h * 128;  // + c*16384 + w
#pragma unroll
    for (int i = 0; i < 32; i++) {
        int idx = t + i * 256;
        s_W[idx] = g_WinT[idx];
        int c = idx >> 7, w = idx & 127;
        s_F[idx] = xrow[c * 16384 + w] + alpha * s_pr[w];
    }
    __syncthreads();

    const int tx = t & 15, ty = t >> 4;
    const int o0 = tx * 8, w0 = ty * 8;

    u64 acc[4][8];
#pragma unroll
    for (int op = 0; op < 4; op++)
#pragma unroll
        for (int j = 0; j < 8; j++) acc[op][j] = 0ull;

#pragma unroll 4
    for (int k = 0; k < 64; k++) {
        const float* wr = &s_W[k * 128 + o0];
        ulonglong2 wa = *(const ulonglong2*)(wr);
        ulonglong2 wb = *(const ulonglong2*)(wr + 4);
        u64 a2[4] = { wa.x, wa.y, wb.x, wb.y };

        float4 f0 = *(const float4*)&s_F[k * 128 + w0];
        float4 f1 = *(const float4*)&s_F[k * 128 + w0 + 4];
        u64 bd[8];
        bd[0] = pack2(f0.x, f0.x); bd[1] = pack2(f0.y, f0.y);
        bd[2] = pack2(f0.z, f0.z); bd[3] = pack2(f0.w, f0.w);
        bd[4] = pack2(f1.x, f1.x); bd[5] = pack2(f1.y, f1.y);
        bd[6] = pack2(f1.z, f1.z); bd[7] = pack2(f1.w, f1.w);

#pragma unroll
        for (int op = 0; op < 4; op++)
#pragma unroll
            for (int j = 0; j < 8; j++) ffma2(acc[op][j], a2[op], bd[j]);
    }
    {   // + b_in
        ulonglong2 bb0 = *(const ulonglong2*)&b_in[o0];
        ulonglong2 bb1 = *(const ulonglong2*)&b_in[o0 + 4];
        u64 bb[4] = { bb0.x, bb0.y, bb1.x, bb1.y };
#pragma unroll
        for (int op = 0; op < 4; op++)
#pragma unroll
            for (int j = 0; j < 8; j++) acc[op][j] = add2(acc[op][j], bb[op]);
    }
    __syncthreads();   // done reading s_W/s_F

#pragma unroll
    for (int j = 0; j < 8; j++) {
        ulonglong2 v0, v1;
        v0.x = acc[0][j]; v0.y = acc[1][j];
        v1.x = acc[2][j]; v1.y = acc[3][j];
        *(ulonglong2*)&s_P[(w0 + j) * 128 + o0]     = v0;
        *(ulonglong2*)&s_P[(w0 + j) * 128 + o0 + 4] = v1;
    }
    __syncthreads();

    // coalesced x_proj write-out
    float* xp_row = g_xp + ((long)b * 128 + h) * 16384;
    {
        float4* dst = (float4*)xp_row;
        const float4* src = (const float4*)s_P;
#pragma unroll
        for (int i = 0; i < 16; i++) dst[t + i * 256] = src[t + i * 256];
    }

    // horizontal scan: 1 thread per hid channel, conflict-free LDS,
    // coalesced 512B global stores per step
    if (t < 128) {
        const float a = g_At[t];
        const float bv = Bvec[t];
        float st = 0.0f;
        float* hs_row = g_hs + ((long)b * 128 + h) * 16384;
        for (int w = 0; w < 128; w++) {
            st = fmaf(a, st, bv * s_P[w * 128 + t]);
            hs_row[w * 128 + t] = st;
        }
    }
}

// ---- K2: vertical scan, h_sum = h_hor + h_ver (in place) ----
__global__ __launch_bounds__(256) void k_vscan(const float* __restrict__ Bvec) {
    int g = blockIdx.x * 256 + threadIdx.x;   // 131072 threads = b*w*o
    int b = g >> 14;
    int w = (g >> 7) & 127;
    int o = g & 127;
    const float a = g_At[o];
    const float bv = Bvec[o];
    float st = 0.0f;
    long base = (long)b * 2097152 + w * 128 + o;
#pragma unroll 4
    for (int h = 0; h < 128; h++) {
        long idx = base + (long)h * 16384;
        float xpv = g_xp[idx];
        st = fmaf(a, st, bv * xpv);
        g_hs[idx] += st;
    }
}

// ---- K3: per-(b,h) row: GEMM2 (HID=128 -> C=64) + fused epilogue ----
// grid(128,8), 256 thr, 96KB dyn smem.
__global__ __launch_bounds__(256) void k_outproj(
    const float* __restrict__ x, const float* __restrict__ prior,
    const float* __restrict__ b_out, const float* __restrict__ alpha_p,
    const float* __restrict__ gamma_p, float* __restrict__ out)
{
    extern __shared__ float smem[];
    float* s_WO = smem;            // [o*64 + c]   32KB
    float* s_G  = smem + 8192;     // [w*128 + o]  64KB
    __shared__ float s_pr[128];

    const int t = threadIdx.x;
    const int h = blockIdx.x, b = blockIdx.y;
    const float alpha = __ldg(alpha_p), gamma = __ldg(gamma_p);

    if (t < 128) s_pr[t] = prior_at(prior, b, h, t);
    {
        const float4* src = (const float4*)g_WoutT;
        float4* dst = (float4*)s_WO;
#pragma unroll
        for (int i = 0; i < 8; i++) dst[t + i * 256] = src[t + i * 256];
    }
    {
        const float4* src = (const float4*)(g_hs + ((long)b * 128 + h) * 16384);
        float4* dst = (float4*)s_G;
#pragma unroll
        for (int i = 0; i < 16; i++) dst[t + i * 256] = src[t + i * 256];
    }
    __syncthreads();

    const int tx = t & 7, ty = t >> 3;
    const int c0 = tx * 8, w0 = ty * 4;

    u64 acc[4][4];
#pragma unroll
    for (int cp = 0; cp < 4; cp++)
#pragma unroll
        for (int j = 0; j < 4; j++) acc[cp][j] = 0ull;

#pragma unroll 4
    for (int k = 0; k < 128; k++) {
        const float* wr = &s_WO[k * 64 + c0];
        ulonglong2 wa = *(const ulonglong2*)(wr);
        ulonglong2 wb = *(const ulonglong2*)(wr + 4);
        u64 a2[4] = { wa.x, wa.y, wb.x, wb.y };
        u64 bd[4];
#pragma unroll
        for (int j = 0; j < 4; j++) {
            float g = s_G[(w0 + j) * 128 + k];
            bd[j] = pack2(g, g);
        }
#pragma unroll
        for (int cp = 0; cp < 4; cp++)
#pragma unroll
            for (int j = 0; j < 4; j++) ffma2(acc[cp][j], a2[cp], bd[j]);
    }

    float bo[8];
    {
        float4 b0 = *(const float4*)&b_out[c0];
        float4 b1 = *(const float4*)&b_out[c0 + 4];
        bo[0]=b0.x; bo[1]=b0.y; bo[2]=b0.z; bo[3]=b0.w;
        bo[4]=b1.x; bo[5]=b1.y; bo[6]=b1.z; bo[7]=b1.w;
    }
    float res[8][4];
#pragma unroll
    for (int cp = 0; cp < 4; cp++)
#pragma unroll
        for (int j = 0; j < 4; j++) {
            float2 v = unpack2(acc[cp][j]);
            res[2*cp][j]   = v.x;
            res[2*cp+1][j] = v.y;
        }
    float pr0 = s_pr[w0], pr1 = s_pr[w0+1], pr2 = s_pr[w0+2], pr3 = s_pr[w0+3];
#pragma unroll
    for (int c = 0; c < 8; c++) {
        int cc = c0 + c;
        long base = (((long)b * 64 + cc) * 128 + h) * 128 + w0;
        float4 xv = *(const float4*)&x[base];
        float4 r;
        r.x = fmaf(alpha, pr0, xv.x) + gamma * (res[c][0] + bo[c]);
        r.y = fmaf(alpha, pr1, xv.y) + gamma * (res[c][1] + bo[c]);
        r.z = fmaf(alpha, pr2, xv.z) + gamma * (res[c][2] + bo[c]);
        r.w = fmaf(alpha, pr3, xv.w) + gamma * (res[c][3] + bo[c]);
        *(float4*)&out[base] = r;
    }
}

extern "C" void kernel_launch(void* const* d_in, const int* in_sizes, int n_in,
                              void* d_out, int out_size) {
    const float* x      = (const float*)d_in[0];
    const float* prior  = (const float*)d_in[1];
    const float* W_in   = (const float*)d_in[2];
    const float* b_in   = (const float*)d_in[3];
    const float* A      = (const float*)d_in[4];
    const float* B      = (const float*)d_in[5];
    const float* alpha  = (const float*)d_in[6];
    const float* gamma  = (const float*)d_in[7];
    const float* W_out  = (const float*)d_in[8];
    const float* b_out  = (const float*)d_in[9];
    float* out = (float*)d_out;

    cudaFuncSetAttribute(k_proj_hscan,
        cudaFuncAttributeMaxDynamicSharedMemorySize, 65536);
    cudaFuncSetAttribute(k_outproj,
        cudaFuncAttributeMaxDynamicSharedMemorySize, 98304);

    k_setup<<<32, 256>>>(W_in, W_out, A);
    dim3 grid(HDIM, BSZ);
    k_proj_hscan<<<grid, 256, 65536>>>(x, prior, b_in, B, alpha);
    k_vscan<<<512, 256>>>(B);
    k_outproj<<<grid, 256, 98304>>>(x, prior, b_out, alpha, gamma, out);
}

// round 5
// speedup vs baseline: 1.0156x; 1.0156x over previous
#include <cuda_runtime.h>

#define BSZ 8
#define CDIM 64
#define HDIM 128
#define WDIM 128
#define HID 128

// ---- scratch (device globals; allocation-free) ----
__device__ float g_xp[BSZ*HDIM*WDIM*HID];   // x_proj [b][h][w][o]
__device__ float g_hs[BSZ*HDIM*WDIM*HID];   // h_hor -> h_sum, same layout
__device__ float g_WinT[64*128];            // [k=c][o]
__device__ float g_WoutT[128*64];            // [o][c]
__device__ float g_At[128];                 // tanh(A)

typedef unsigned long long u64;

// ---- packed f32x2 (FFMA2) helpers ----
__device__ __forceinline__ u64 pack2(float lo, float hi) {
    u64 r;
    asm("mov.b64 %0, {%1, %2};" : "=l"(r)
        : "r"(__float_as_uint(lo)), "r"(__float_as_uint(hi)));
    return r;
}
__device__ __forceinline__ float2 unpack2(u64 v) {
    unsigned int a, b;
    asm("mov.b64 {%0, %1}, %2;" : "=r"(a), "=r"(b) : "l"(v));
    return make_float2(__uint_as_float(a), __uint_as_float(b));
}
__device__ __forceinline__ void ffma2(u64& d, u64 a, u64 b) {
    asm("fma.rn.f32x2 %0, %1, %2, %0;" : "+l"(d) : "l"(a), "l"(b));
}
__device__ __forceinline__ u64 add2(u64 a, u64 b) {
    u64 r;
    asm("add.rn.f32x2 %0, %1, %2;" : "=l"(r) : "l"(a), "l"(b));
    return r;
}

// ---- bilinear prior 32->128, align_corners, clip ----
__device__ __forceinline__ float prior_at(const float* __restrict__ prior,
                                          int b, int h, int w) {
    const float s = 31.0f / 127.0f;
    float ys = h * s, xs = w * s;
    int y0 = (int)ys, x0 = (int)xs;
    int y1 = min(y0 + 1, 31), x1 = min(x0 + 1, 31);
    float wy = ys - (float)y0, wx = xs - (float)x0;
    const float* p = prior + b * 1024;
    float p00 = p[y0*32+x0], p01 = p[y0*32+x1];
    float p10 = p[y1*32+x0], p11 = p[y1*32+x1];
    float top = p00 + (p01 - p00) * wx;
    float bot = p10 + (p11 - p10) * wx;
    float v = top + (bot - top) * wy;
    return fminf(1.0f, fmaxf(-1.0f, v));
}

// ---- K0: weight transposes + tanh(A) ----
__global__ void k_setup(const float* __restrict__ Win,
                        const float* __restrict__ Wout,
                        const float* __restrict__ A) {
    int i = blockIdx.x * 256 + threadIdx.x;
    if (i < 64 * 128) {
        int o = i & 127, k = i >> 7;
        g_WinT[i] = Win[o * 64 + k];
        int oo = i >> 6, c = i & 63;
        g_WoutT[i] = Wout[c * 128 + oo];
    }
    if (i < 128) g_At[i] = tanhf(A[i]);
}

// ---- K1: per-(b,h) row: GEMM1 (C=64 -> HID=128) + bias, h-scan ----
// grid(128,8), 256 thr, 64KB dyn smem.
__global__ __launch_bounds__(256) void k_proj_hscan(
    const float* __restrict__ x, const float* __restrict__ prior,
    const float* __restrict__ b_in, const float* __restrict__ Bvec,
    const float* __restrict__ alpha_p)
{
    extern __shared__ float smem[];
    float* s_W = smem;          // [k*128 + o]   32KB
    float* s_F = smem + 8192;   // [k*128 + w]   32KB
    float* s_P = smem;          // [w*128 + o]   64KB (reuse)
    __shared__ float s_pr[128];

    const int t = threadIdx.x;
    const int h = blockIdx.x, b = blockIdx.y;
    const float alpha = __ldg(alpha_p);

    if (t < 128) s_pr[t] = prior_at(prior, b, h, t);
    __syncthreads();

    const float* xrow = x + (long)b * 1048576 + h * 128;  // + c*16384 + w
#pragma unroll
    for (int i = 0; i < 32; i++) {
        int idx = t + i * 256;
        s_W[idx] = g_WinT[idx];
        int c = idx >> 7, w = idx & 127;
        s_F[idx] = xrow[c * 16384 + w] + alpha * s_pr[w];
    }
    __syncthreads();

    const int tx = t & 15, ty = t >> 4;
    const int o0 = tx * 8, w0 = ty * 8;

    u64 acc[4][8];
#pragma unroll
    for (int op = 0; op < 4; op++)
#pragma unroll
        for (int j = 0; j < 8; j++) acc[op][j] = 0ull;

#pragma unroll 4
    for (int k = 0; k < 64; k++) {
        const float* wr = &s_W[k * 128 + o0];
        ulonglong2 wa = *(const ulonglong2*)(wr);
        ulonglong2 wb = *(const ulonglong2*)(wr + 4);
        u64 a2[4] = { wa.x, wa.y, wb.x, wb.y };

        float4 f0 = *(const float4*)&s_F[k * 128 + w0];
        float4 f1 = *(const float4*)&s_F[k * 128 + w0 + 4];
        u64 bd[8];
        bd[0] = pack2(f0.x, f0.x); bd[1] = pack2(f0.y, f0.y);
        bd[2] = pack2(f0.z, f0.z); bd[3] = pack2(f0.w, f0.w);
        bd[4] = pack2(f1.x, f1.x); bd[5] = pack2(f1.y, f1.y);
        bd[6] = pack2(f1.z, f1.z); bd[7] = pack2(f1.w, f1.w);

#pragma unroll
        for (int op = 0; op < 4; op++)
#pragma unroll
            for (int j = 0; j < 8; j++) ffma2(acc[op][j], a2[op], bd[j]);
    }
    {   // + b_in
        ulonglong2 bb0 = *(const ulonglong2*)&b_in[o0];
        ulonglong2 bb1 = *(const ulonglong2*)&b_in[o0 + 4];
        u64 bb[4] = { bb0.x, bb0.y, bb1.x, bb1.y };
#pragma unroll
        for (int op = 0; op < 4; op++)
#pragma unroll
            for (int j = 0; j < 8; j++) acc[op][j] = add2(acc[op][j], bb[op]);
    }
    __syncthreads();   // done reading s_W/s_F

#pragma unroll
    for (int j = 0; j < 8; j++) {
        ulonglong2 v0, v1;
        v0.x = acc[0][j]; v0.y = acc[1][j];
        v1.x = acc[2][j]; v1.y = acc[3][j];
        *(ulonglong2*)&s_P[(w0 + j) * 128 + o0]     = v0;
        *(ulonglong2*)&s_P[(w0 + j) * 128 + o0 + 4] = v1;
    }
    __syncthreads();

    // coalesced x_proj write-out
    float* xp_row = g_xp + ((long)b * 128 + h) * 16384;
    {
        float4* dst = (float4*)xp_row;
        const float4* src = (const float4*)s_P;
#pragma unroll
        for (int i = 0; i < 16; i++) dst[t + i * 256] = src[t + i * 256];
    }

    // horizontal scan: 1 thread per hid channel, conflict-free LDS,
    // coalesced 512B global stores per step
    if (t < 128) {
        const float a = g_At[t];
        const float bv = Bvec[t];
        float st = 0.0f;
        float* hs_row = g_hs + ((long)b * 128 + h) * 16384;
        for (int w = 0; w < 128; w++) {
            st = fmaf(a, st, bv * s_P[w * 128 + t]);
            hs_row[w * 128 + t] = st;
        }
    }
}

// ---- K2: vertical scan, h_sum = h_hor + h_ver (in place), float4 ----
__global__ __launch_bounds__(256) void k_vscan(const float* __restrict__ Bvec) {
    int g = blockIdx.x * 256 + threadIdx.x;   // 32768 threads = b*w*o4
    int b  = g >> 12;
    int w  = (g >> 5) & 127;
    int o4 = g & 31;
    float4 a4 = *(const float4*)&g_At[o4 * 4];
    float4 b4 = *(const float4*)&Bvec[o4 * 4];
    float4 st = make_float4(0.f, 0.f, 0.f, 0.f);
    long base = (long)b * 2097152 + w * 128 + o4 * 4;
#pragma unroll 8
    for (int h = 0; h < 128; h++) {
        long idx = base + (long)h * 16384;
        float4 xp = *(const float4*)&g_xp[idx];
        st.x = fmaf(a4.x, st.x, b4.x * xp.x);
        st.y = fmaf(a4.y, st.y, b4.y * xp.y);
        st.z = fmaf(a4.z, st.z, b4.z * xp.z);
        st.w = fmaf(a4.w, st.w, b4.w * xp.w);
        float4 hv = *(const float4*)&g_hs[idx];
        hv.x += st.x; hv.y += st.y; hv.z += st.z; hv.w += st.w;
        *(float4*)&g_hs[idx] = hv;
    }
}

// ---- K3: per-(b,h) row: GEMM2 (HID=128 -> C=64) + fused epilogue ----
// grid(128,8), 256 thr. smem: s_WO [k][64] 32KB + s_G [w][132-pad] 66KB.
// k-blocked by 4: G operand loaded as float4 along k (contiguous, padded rows
// break the same-bank pattern across w rows) -> crossbar < FMA, FFMA2-bound.
#define SG_STRIDE 132
__global__ __launch_bounds__(256) void k_outproj(
    const float* __restrict__ x, const float* __restrict__ prior,
    const float* __restrict__ b_out, const float* __restrict__ alpha_p,
    const float* __restrict__ gamma_p, float* __restrict__ out)
{
    extern __shared__ float smem[];
    float* s_WO = smem;            // [k*64 + c]        8192 floats
    float* s_G  = smem + 8192;     // [w*SG_STRIDE + k] 16896 floats
    __shared__ float s_pr[128];

    const int t = threadIdx.x;
    const int h = blockIdx.x, b = blockIdx.y;
    const float alpha = __ldg(alpha_p), gamma = __ldg(gamma_p);

    if (t < 128) s_pr[t] = prior_at(prior, b, h, t);
    {   // stage weights [k][c], vectorized, conflict-free
        const float4* src = (const float4*)g_WoutT;
        float4* dst = (float4*)s_WO;
#pragma unroll
        for (int i = 0; i < 8; i++) dst[t + i * 256] = src[t + i * 256];
    }
    {   // stage h_sum row into padded [w][k] (contiguous float4 STS)
        const float4* src = (const float4*)(g_hs + ((long)b * 128 + h) * 16384);
#pragma unroll
        for (int i = 0; i < 16; i++) {
            int idx = t + i * 256;
            float4 v = src[idx];
            int w = idx >> 5, o4 = idx & 31;
            *(float4*)&s_G[w * SG_STRIDE + o4 * 4] = v;
        }
    }
    __syncthreads();

    const int tx = t & 7, ty = t >> 3;     // 8 c-tiles x 32 w-tiles
    const int c0 = tx * 8, w0 = ty * 4;

    u64 acc[4][4];
#pragma unroll
    for (int cp = 0; cp < 4; cp++)
#pragma unroll
        for (int j = 0; j < 4; j++) acc[cp][j] = 0ull;

#pragma unroll 2
    for (int k4 = 0; k4 < 32; k4++) {
        const int kb = k4 * 4;
        float gm[4][4];
#pragma unroll
        for (int j = 0; j < 4; j++)
            *(float4*)gm[j] = *(const float4*)&s_G[(w0 + j) * SG_STRIDE + kb];

#pragma unroll
        for (int kk = 0; kk < 4; kk++) {
            const float* wr = &s_WO[(kb + kk) * 64 + c0];
            ulonglong2 wa = *(const ulonglong2*)(wr);
            ulonglong2 wb = *(const ulonglong2*)(wr + 4);
            u64 a2[4] = { wa.x, wa.y, wb.x, wb.y };
            u64 bd[4];
#pragma unroll
            for (int j = 0; j < 4; j++) bd[j] = pack2(gm[j][kk], gm[j][kk]);
#pragma unroll
            for (int cp = 0; cp < 4; cp++)
#pragma unroll
                for (int j = 0; j < 4; j++) ffma2(acc[cp][j], a2[cp], bd[j]);
        }
    }

    float bo[8];
    {
        float4 b0 = *(const float4*)&b_out[c0];
        float4 b1 = *(const float4*)&b_out[c0 + 4];
        bo[0]=b0.x; bo[1]=b0.y; bo[2]=b0.z; bo[3]=b0.w;
        bo[4]=b1.x; bo[5]=b1.y; bo[6]=b1.z; bo[7]=b1.w;
    }
    float res[8][4];
#pragma unroll
    for (int cp = 0; cp < 4; cp++)
#pragma unroll
        for (int j = 0; j < 4; j++) {
            float2 v = unpack2(acc[cp][j]);
            res[2*cp][j]   = v.x;
            res[2*cp+1][j] = v.y;
        }
    float pr0 = s_pr[w0], pr1 = s_pr[w0+1], pr2 = s_pr[w0+2], pr3 = s_pr[w0+3];
#pragma unroll
    for (int c = 0; c < 8; c++) {
        int cc = c0 + c;
        long base = (((long)b * 64 + cc) * 128 + h) * 128 + w0;
        float4 xv = *(const float4*)&x[base];
        float4 r;
        r.x = fmaf(alpha, pr0, xv.x) + gamma * (res[c][0] + bo[c]);
        r.y = fmaf(alpha, pr1, xv.y) + gamma * (res[c][1] + bo[c]);
        r.z = fmaf(alpha, pr2, xv.z) + gamma * (res[c][2] + bo[c]);
        r.w = fmaf(alpha, pr3, xv.w) + gamma * (res[c][3] + bo[c]);
        *(float4*)&out[base] = r;
    }
}

extern "C" void kernel_launch(void* const* d_in, const int* in_sizes, int n_in,
                              void* d_out, int out_size) {
    const float* x      = (const float*)d_in[0];
    const float* prior  = (const float*)d_in[1];
    const float* W_in   = (const float*)d_in[2];
    const float* b_in   = (const float*)d_in[3];
    const float* A      = (const float*)d_in[4];
    const float* B      = (const float*)d_in[5];
    const float* alpha  = (const float*)d_in[6];
    const float* gamma  = (const float*)d_in[7];
    const float* W_out  = (const float*)d_in[8];
    const float* b_out  = (const float*)d_in[9];
    float* out = (float*)d_out;

    const int smem_k1 = 65536;
    const int smem_k3 = (8192 + 128 * SG_STRIDE) * 4;   // 100352 B

    cudaFuncSetAttribute(k_proj_hscan,
        cudaFuncAttributeMaxDynamicSharedMemorySize, smem_k1);
    cudaFuncSetAttribute(k_outproj,
        cudaFuncAttributeMaxDynamicSharedMemorySize, smem_k3);

    k_setup<<<32, 256>>>(W_in, W_out, A);
    dim3 grid(HDIM, BSZ);
    k_proj_hscan<<<grid, 256, smem_k1>>>(x, prior, b_in, B, alpha);
    k_vscan<<<128, 256>>>(B);
    k_outproj<<<grid, 256, smem_k3>>>(x, prior, b_out, alpha, gamma, out);
}

// round 7
// speedup vs baseline: 2.4678x; 2.4298x over previous
#include <cuda_runtime.h>
#include <cuda_bf16.h>
#include <cstdint>

#define BSZ 8
#define CDIM 64
#define HDIM 128
#define WDIM 128
#define HID 128

// smem strides (bf16 elems), +8 padding keeps ldmatrix conflict-free
#define LDA1 136   // K1 A: [c][w], 64 rows
#define LDB1 72    // K1 B: [o][c], 128 rows
#define LDA3 136   // K3 A: [o][w], 128 rows
#define LDB3 136   // K3 B: [c][o], 64 rows
#define LDP  132   // fp32 staging [o][w] / [c][w]

// ---- scratch (device globals; allocation-free) ----
__device__ __nv_bfloat16 g_xp[BSZ*HDIM*HID*WDIM];  // x_proj [b][h][o][w] bf16
__device__ __nv_bfloat16 g_hs[BSZ*HDIM*HID*WDIM];  // h_hor -> h_sum
__device__ __align__(16) __nv_bfloat16 g_WinP[HID*LDB1];    // [o][c] padded
__device__ __align__(16) __nv_bfloat16 g_WoutP[CDIM*LDB3];  // [c][o] padded
__device__ float g_At[HID];

__device__ __forceinline__ uint32_t smem_u32(const void* p) {
    return (uint32_t)__cvta_generic_to_shared(p);
}

// ---- ldmatrix / mma.sync wrappers (sm_80-portable) ----
__device__ __forceinline__ void ldsm_x4_trans(uint32_t* r, uint32_t a) {
    asm volatile("ldmatrix.sync.aligned.m8n8.x4.trans.shared.b16 {%0,%1,%2,%3}, [%4];"
        : "=r"(r[0]), "=r"(r[1]), "=r"(r[2]), "=r"(r[3]) : "r"(a));
}
__device__ __forceinline__ void ldsm_x2(uint32_t* r, uint32_t a) {
    asm volatile("ldmatrix.sync.aligned.m8n8.x2.shared.b16 {%0,%1}, [%2];"
        : "=r"(r[0]), "=r"(r[1]) : "r"(a));
}
__device__ __forceinline__ void mma_bf16(float* d, const uint32_t* a, const uint32_t* b) {
    asm volatile("mma.sync.aligned.m16n8k16.row.col.f32.bf16.bf16.f32 "
        "{%0,%1,%2,%3}, {%4,%5,%6,%7}, {%8,%9}, {%0,%1,%2,%3};"
        : "+f"(d[0]), "+f"(d[1]), "+f"(d[2]), "+f"(d[3])
        : "r"(a[0]), "r"(a[1]), "r"(a[2]), "r"(a[3]), "r"(b[0]), "r"(b[1]));
}

// ---- bilinear prior 32->128, align_corners, clip ----
__device__ __forceinline__ float prior_at(const float* __restrict__ prior,
                                          int b, int h, int w) {
    const float s = 31.0f / 127.0f;
    float ys = h * s, xs = w * s;
    int y0 = (int)ys, x0 = (int)xs;
    int y1 = min(y0 + 1, 31), x1 = min(x0 + 1, 31);
    float wy = ys - (float)y0, wx = xs - (float)x0;
    const float* p = prior + b * 1024;
    float p00 = p[y0*32+x0], p01 = p[y0*32+x1];
    float p10 = p[y1*32+x0], p11 = p[y1*32+x1];
    float top = p00 + (p01 - p00) * wx;
    float bot = p10 + (p11 - p10) * wx;
    float v = top + (bot - top) * wy;
    return fminf(1.0f, fmaxf(-1.0f, v));
}

// ---- K0: weights -> padded bf16 layouts + tanh(A) ----
__global__ void k_setup(const float* __restrict__ Win,
                        const float* __restrict__ Wout,
                        const float* __restrict__ A) {
    int i = blockIdx.x * 256 + threadIdx.x;
    if (i < 8192) {
        int o = i >> 6, c = i & 63;
        g_WinP[o * LDB1 + c] = __float2bfloat16(Win[o * 64 + c]);
        int cc = i >> 7, oo = i & 127;
        g_WoutP[cc * LDB3 + oo] = __float2bfloat16(Wout[cc * 128 + oo]);
    }
    if (i < 128) g_At[i] = tanhf(A[i]);
}

// ---- K1: per-(b,h): x_proj = F_mod @ Win^T + b_in (HMMA), h-scan ----
// smem: sA [64c][136w] bf16 17408B @0 ; sB [128o][72c] bf16 18432B @17408
//       sP [128o][132w] f32 67584B overlays everything after the MMA.
__global__ __launch_bounds__(256) void k1(
    const float* __restrict__ x, const float* __restrict__ prior,
    const float* __restrict__ b_in, const float* __restrict__ Bvec,
    const float* __restrict__ alpha_p)
{
    extern __shared__ __align__(16) char smch[];
    __nv_bfloat16* sA = (__nv_bfloat16*)smch;
    __nv_bfloat16* sB = (__nv_bfloat16*)(smch + 17408);
    float* sP = (float*)smch;
    __shared__ float s_pr[128], s_bin[128];

    const int t = threadIdx.x;
    const int wid = t >> 5, lid = t & 31;
    const int h = blockIdx.x, b = blockIdx.y;
    const float alpha = __ldg(alpha_p);

    if (t < 128) { s_pr[t] = prior_at(prior, b, h, t); s_bin[t] = b_in[t]; }
    __syncthreads();

    {   // sB <- Win padded (linear copy, 1152 uint4)
        const uint4* src = (const uint4*)g_WinP;
        uint4* dst = (uint4*)sB;
#pragma unroll
        for (int i = 0; i < 5; i++) {
            int idx = t + i * 256;
            if (idx < 1152) dst[idx] = src[idx];
        }
    }
    {   // sA <- F_mod bf16 [c][w]; thread: (c, w-pair)
        const float* xrow = x + (long)b * 1048576 + h * 128;
#pragma unroll
        for (int i = 0; i < 16; i++) {
            int idx = t + i * 256;           // 4096 = 64c x 64 wp
            int c = idx >> 6, wp = idx & 63;
            float2 f = *(const float2*)&xrow[c * 16384 + 2 * wp];
            f.x += alpha * s_pr[2 * wp];
            f.y += alpha * s_pr[2 * wp + 1];
            *(__nv_bfloat162*)&sA[c * LDA1 + 2 * wp] = __float22bfloat162_rn(f);
        }
    }
    __syncthreads();

    // MMA: warp wid owns m-rows w0..w0+15, full N=128, K=64
    const int w0 = wid * 16;
    float acc[16][4];
#pragma unroll
    for (int nt = 0; nt < 16; nt++)
#pragma unroll
        for (int j = 0; j < 4; j++) acc[nt][j] = 0.f;

    const uint32_t sA_u = smem_u32(sA), sB_u = smem_u32(sB);
    // A (trans from [c][w]): lane -> row c-in-tile, col w-offset
    const int a_row = (lid & 7) + ((lid >> 4) << 3);
    const int a_col = ((lid >> 3) & 1) << 3;
    const uint32_t a_base = sA_u + (uint32_t)((a_row * LDA1 + w0 + a_col) * 2);
    // B (no-trans from [o][c]): lanes 0-15 meaningful
    const int lb = lid & 15;
    const uint32_t b_base = sB_u + (uint32_t)(((lb & 7) * LDB1 + ((lb >> 3) << 3)) * 2);

#pragma unroll
    for (int ks = 0; ks < 4; ks++) {
        uint32_t afr[4];
        ldsm_x4_trans(afr, a_base + (uint32_t)(ks * 16 * LDA1 * 2));
#pragma unroll
        for (int nt = 0; nt < 16; nt++) {
            uint32_t bfr[2];
            ldsm_x2(bfr, b_base + (uint32_t)((nt * 8 * LDB1 + ks * 16) * 2));
            mma_bf16(acc[nt], afr, bfr);
        }
    }
    __syncthreads();   // frags in regs; safe to overlay sP

    {   // acc -> sP[o][w] (+bias)
        const int g = lid >> 2, q2 = (lid & 3) * 2;
        const int w = w0 + g;
#pragma unroll
        for (int nt = 0; nt < 16; nt++) {
            int o = nt * 8 + q2;
            sP[o * LDP + w]           = acc[nt][0] + s_bin[o];
            sP[(o + 1) * LDP + w]     = acc[nt][1] + s_bin[o + 1];
            sP[o * LDP + w + 8]       = acc[nt][2] + s_bin[o];
            sP[(o + 1) * LDP + w + 8] = acc[nt][3] + s_bin[o + 1];
        }
    }
    __syncthreads();

    {   // x_proj bf16 write-out, coalesced
        __nv_bfloat16* xp = g_xp + ((long)b * 128 + h) * 16384;
#pragma unroll
        for (int i = 0; i < 16; i++) {
            int idx = t + i * 256;
            int o = idx >> 5, w4 = idx & 31;
            float4 v = *(const float4*)&sP[o * LDP + w4 * 4];
            __nv_bfloat162 p0 = __float22bfloat162_rn(make_float2(v.x, v.y));
            __nv_bfloat162 p1 = __float22bfloat162_rn(make_float2(v.z, v.w));
            uint2 u = make_uint2(*(uint32_t*)&p0, *(uint32_t*)&p1);
            *(uint2*)&xp[o * 128 + w4 * 4] = u;
        }
    }
    __syncthreads();

    if (t < 128) {   // h-scan along w in sP, float4 batches
        const float a = g_At[t], bv = Bvec[t];
        float st = 0.0f;
        float* row = &sP[t * LDP];
#pragma unroll 4
        for (int wb = 0; wb < 32; wb++) {
            float4 v = *(const float4*)&row[wb * 4];
            st = fmaf(a, st, bv * v.x); v.x = st;
            st = fmaf(a, st, bv * v.y); v.y = st;
            st = fmaf(a, st, bv * v.z); v.z = st;
            st = fmaf(a, st, bv * v.w); v.w = st;
            *(float4*)&row[wb * 4] = v;
        }
    }
    __syncthreads();

    {   // h_hor bf16 write-out
        __nv_bfloat16* hs = g_hs + ((long)b * 128 + h) * 16384;
#pragma unroll
        for (int i = 0; i < 16; i++) {
            int idx = t + i * 256;
            int o = idx >> 5, w4 = idx & 31;
            float4 v = *(const float4*)&sP[o * LDP + w4 * 4];
            __nv_bfloat162 p0 = __float22bfloat162_rn(make_float2(v.x, v.y));
            __nv_bfloat162 p1 = __float22bfloat162_rn(make_float2(v.z, v.w));
            uint2 u = make_uint2(*(uint32_t*)&p0, *(uint32_t*)&p1);
            *(uint2*)&hs[o * 128 + w4 * 4] = u;
        }
    }
}

// ---- K2: vertical scan, h_sum = h_hor + h_ver (in place, bf16) ----
// 256 blocks x 128 thr; thread owns (b,o,4w), fp32 states.
__global__ __launch_bounds__(128) void k2(const float* __restrict__ Bvec) {
    int g = blockIdx.x * 128 + threadIdx.x;   // 32768 = b(8) x o(128) x w4(32)
    int b = g >> 12;
    int o = (g >> 5) & 127;
    int w4 = g & 31;
    const float a = g_At[o], bv = Bvec[o];
    float st0 = 0.f, st1 = 0.f, st2 = 0.f, st3 = 0.f;
    long base = ((long)b * 128) * 16384 + o * 128 + w4 * 4;
#pragma unroll 4
    for (int h = 0; h < 128; h++) {
        long idx = base + (long)h * 16384;
        uint2 u = *(const uint2*)&g_xp[idx];
        float2 f0 = __bfloat1622float2(*(__nv_bfloat162*)&u.x);
        float2 f1 = __bfloat1622float2(*(__nv_bfloat162*)&u.y);
        st0 = fmaf(a, st0, bv * f0.x);
        st1 = fmaf(a, st1, bv * f0.y);
        st2 = fmaf(a, st2, bv * f1.x);
        st3 = fmaf(a, st3, bv * f1.y);
        uint2 hu = *(const uint2*)&g_hs[idx];
        float2 h0 = __bfloat1622float2(*(__nv_bfloat162*)&hu.x);
        float2 h1 = __bfloat1622float2(*(__nv_bfloat162*)&hu.y);
        h0.x += st0; h0.y += st1; h1.x += st2; h1.y += st3;
        __nv_bfloat162 p0 = __float22bfloat162_rn(h0);
        __nv_bfloat162 p1 = __float22bfloat162_rn(h1);
        *(uint2*)&g_hs[idx] = make_uint2(*(uint32_t*)&p0, *(uint32_t*)&p1);
    }
}

// ---- K3: per-(b,h): out = h_sum @ Wout^T (HMMA), fused epilogue ----
// smem: sA [128o][136w] bf16 34816B @0 ; sB [64c][136o] bf16 17408B @34816
//       sR [64c][132w] f32 33792B overlays sA after MMA.
__global__ __launch_bounds__(256) void k3(
    const float* __restrict__ x, const float* __restrict__ prior,
    const float* __restrict__ b_out, const float* __restrict__ alpha_p,
    const float* __restrict__ gamma_p, float* __restrict__ out)
{
    extern __shared__ __align__(16) char smch[];
    __nv_bfloat16* sA = (__nv_bfloat16*)smch;
    __nv_bfloat16* sB = (__nv_bfloat16*)(smch + 34816);
    float* sR = (float*)smch;
    __shared__ float s_pr[128], s_bo[64];

    const int t = threadIdx.x;
    const int wid = t >> 5, lid = t & 31;
    const int h = blockIdx.x, b = blockIdx.y;
    const float alpha = __ldg(alpha_p), gamma = __ldg(gamma_p);

    if (t < 128) s_pr[t] = prior_at(prior, b, h, t);
    if (t < 64) s_bo[t] = b_out[t];

    {   // sB <- Wout padded (1088 uint4)
        const uint4* src = (const uint4*)g_WoutP;
        uint4* dst = (uint4*)sB;
#pragma unroll
        for (int i = 0; i < 5; i++) {
            int idx = t + i * 256;
            if (idx < 1088) dst[idx] = src[idx];
        }
    }
    {   // sA <- h_sum [o][w] (16B chunks into padded rows)
        const __nv_bfloat16* hs = g_hs + ((long)b * 128 + h) * 16384;
#pragma unroll
        for (int i = 0; i < 8; i++) {
            int idx = t + i * 256;           // 2048 = 128o x 16 w8
            int o = idx >> 4, w8 = idx & 15;
            uint4 v = *(const uint4*)&hs[o * 128 + w8 * 8];
            *(uint4*)&sA[o * LDA3 + w8 * 8] = v;
        }
    }
    __syncthreads();

    // MMA: M=128(w) x N=64(c) x K=128(o); warp wid -> m-rows w0..w0+15
    const int w0 = wid * 16;
    float acc[8][4];
#pragma unroll
    for (int nt = 0; nt < 8; nt++)
#pragma unroll
        for (int j = 0; j < 4; j++) acc[nt][j] = 0.f;

    const uint32_t sA_u = smem_u32(sA), sB_u = smem_u32(sB);
    const int a_row = (lid & 7) + ((lid >> 4) << 3);
    const int a_col = ((lid >> 3) & 1) << 3;
    const uint32_t a_base = sA_u + (uint32_t)((a_row * LDA3 + w0 + a_col) * 2);
    const int lb = lid & 15;
    const uint32_t b_base = sB_u + (uint32_t)(((lb & 7) * LDB3 + ((lb >> 3) << 3)) * 2);

#pragma unroll
    for (int ks = 0; ks < 8; ks++) {
        uint32_t afr[4];
        ldsm_x4_trans(afr, a_base + (uint32_t)(ks * 16 * LDA3 * 2));
#pragma unroll
        for (int nt = 0; nt < 8; nt++) {
            uint32_t bfr[2];
            ldsm_x2(bfr, b_base + (uint32_t)((nt * 8 * LDB3 + ks * 16) * 2));
            mma_bf16(acc[nt], afr, bfr);
        }
    }
    __syncthreads();   // overlay sR

    {   // acc -> sR[c][w]
        const int g = lid >> 2, q2 = (lid & 3) * 2;
        const int w = w0 + g;
#pragma unroll
        for (int nt = 0; nt < 8; nt++) {
            int c = nt * 8 + q2;
            sR[c * LDP + w]           = acc[nt][0];
            sR[(c + 1) * LDP + w]     = acc[nt][1];
            sR[c * LDP + w + 8]       = acc[nt][2];
            sR[(c + 1) * LDP + w + 8] = acc[nt][3];
        }
    }
    __syncthreads();

    {   // fused epilogue: out = x + alpha*pr + gamma*(res + b_out)
#pragma unroll
        for (int i = 0; i < 32; i++) {
            int idx = t + i * 256;           // 8192 = 64c x 128w
            int c = idx >> 7, w = idx & 127;
            long gb = (((long)b * 64 + c) * 128 + h) * 128 + w;
            float val = sR[c * LDP + w];
            out[gb] = fmaf(alpha, s_pr[w], x[gb]) + gamma * (val + s_bo[c]);
        }
    }
}

extern "C" void kernel_launch(void* const* d_in, const int* in_sizes, int n_in,
                              void* d_out, int out_size) {
    const float* x      = (const float*)d_in[0];
    const float* prior  = (const float*)d_in[1];
    const float* W_in   = (const float*)d_in[2];
    const float* b_in   = (const float*)d_in[3];
    const float* A      = (const float*)d_in[4];
    const float* B      = (const float*)d_in[5];
    const float* alpha  = (const float*)d_in[6];
    const float* gamma  = (const float*)d_in[7];
    const float* W_out  = (const float*)d_in[8];
    const float* b_out  = (const float*)d_in[9];
    float* out = (float*)d_out;

    const int smem_k1 = 128 * LDP * 4;                 // 67584
    const int smem_k3 = 34816 + 17408;                 // 52224

    cudaFuncSetAttribute(k1, cudaFuncAttributeMaxDynamicSharedMemorySize, smem_k1);
    cudaFuncSetAttribute(k3, cudaFuncAttributeMaxDynamicSharedMemorySize, smem_k3);

    k_setup<<<32, 256>>>(W_in, W_out, A);
    dim3 grid(HDIM, BSZ);
    k1<<<grid, 256, smem_k1>>>(x, prior, b_in, B, alpha);
    k2<<<256, 128>>>(B);
    k3<<<grid, 256, smem_k3>>>(x, prior, b_out, alpha, gamma, out);
}

// round 8
// speedup vs baseline: 3.9848x; 1.6147x over previous
#include <cuda_runtime.h>
#include <cuda_bf16.h>
#include <cstdint>

#define BSZ 8
#define CDIM 64
#define HDIM 128
#define WDIM 128
#define HID 128

// smem strides (bf16 elems), padding keeps ldmatrix / column access conflict-light
#define LDA1 136   // K1 A: [c][w], 64 rows
#define LDB1 72    // K1 B: [o][c], 128 rows
#define LDS1 136   // K1 staging [o][w] bf16
#define LDA3 136   // K3 A: [o][w], 128 rows
#define LDB3 136   // K3 B: [c][o], 64 rows
#define LDP  132   // K3 fp32 staging [c][w]
#define LDK2 136   // K2 planes [h][w] bf16

// ---- scratch (device globals; allocation-free) ----
__device__ __nv_bfloat16 g_xp[BSZ*HDIM*HID*WDIM];  // x_proj [b][h][o][w] bf16
__device__ __nv_bfloat16 g_hs[BSZ*HDIM*HID*WDIM];  // h_sum  [b][h][o][w] bf16
__device__ __align__(16) __nv_bfloat16 g_WinP[HID*LDB1];    // [o][c] padded
__device__ __align__(16) __nv_bfloat16 g_WoutP[CDIM*LDB3];  // [c][o] padded
__device__ float g_At[HID];

__device__ __forceinline__ uint32_t smem_u32(const void* p) {
    return (uint32_t)__cvta_generic_to_shared(p);
}

// ---- ldmatrix / mma.sync wrappers (sm_80-portable) ----
__device__ __forceinline__ void ldsm_x4_trans(uint32_t* r, uint32_t a) {
    asm volatile("ldmatrix.sync.aligned.m8n8.x4.trans.shared.b16 {%0,%1,%2,%3}, [%4];"
        : "=r"(r[0]), "=r"(r[1]), "=r"(r[2]), "=r"(r[3]) : "r"(a));
}
__device__ __forceinline__ void ldsm_x2(uint32_t* r, uint32_t a) {
    asm volatile("ldmatrix.sync.aligned.m8n8.x2.shared.b16 {%0,%1}, [%2];"
        : "=r"(r[0]), "=r"(r[1]) : "r"(a));
}
__device__ __forceinline__ void mma_bf16(float* d, const uint32_t* a, const uint32_t* b) {
    asm volatile("mma.sync.aligned.m16n8k16.row.col.f32.bf16.bf16.f32 "
        "{%0,%1,%2,%3}, {%4,%5,%6,%7}, {%8,%9}, {%0,%1,%2,%3};"
        : "+f"(d[0]), "+f"(d[1]), "+f"(d[2]), "+f"(d[3])
        : "r"(a[0]), "r"(a[1]), "r"(a[2]), "r"(a[3]), "r"(b[0]), "r"(b[1]));
}

// ---- bilinear prior 32->128, align_corners, clip ----
__device__ __forceinline__ float prior_at(const float* __restrict__ prior,
                                          int b, int h, int w) {
    const float s = 31.0f / 127.0f;
    float ys = h * s, xs = w * s;
    int y0 = (int)ys, x0 = (int)xs;
    int y1 = min(y0 + 1, 31), x1 = min(x0 + 1, 31);
    float wy = ys - (float)y0, wx = xs - (float)x0;
    const float* p = prior + b * 1024;
    float p00 = p[y0*32+x0], p01 = p[y0*32+x1];
    float p10 = p[y1*32+x0], p11 = p[y1*32+x1];
    float top = p00 + (p01 - p00) * wx;
    float bot = p10 + (p11 - p10) * wx;
    float v = top + (bot - top) * wy;
    return fminf(1.0f, fmaxf(-1.0f, v));
}

// ---- K0: weights -> padded bf16 layouts + tanh(A) ----
__global__ void k_setup(const float* __restrict__ Win,
                        const float* __restrict__ Wout,
                        const float* __restrict__ A) {
    int i = blockIdx.x * 256 + threadIdx.x;
    if (i < 8192) {
        int o = i >> 6, c = i & 63;
        g_WinP[o * LDB1 + c] = __float2bfloat16(Win[o * 64 + c]);
        int cc = i >> 7, oo = i & 127;
        g_WoutP[cc * LDB3 + oo] = __float2bfloat16(Wout[cc * 128 + oo]);
    }
    if (i < 128) g_At[i] = tanhf(A[i]);
}

// ---- K1: per-(b,h): x_proj = F_mod @ Win^T + b_in (HMMA) ----
// smem: sA [64c][136w] bf16 17408B @0 ; sB [128o][72c] bf16 18432B @17408
//       sPb [128o][136w] bf16 34816B overlays sA after MMA. total 35840B.
__global__ __launch_bounds__(256) void k1(
    const float* __restrict__ x, const float* __restrict__ prior,
    const float* __restrict__ b_in, const float* __restrict__ alpha_p)
{
    extern __shared__ __align__(16) char smch[];
    __nv_bfloat16* sA = (__nv_bfloat16*)smch;
    __nv_bfloat16* sB = (__nv_bfloat16*)(smch + 17408);
    __nv_bfloat16* sPb = (__nv_bfloat16*)smch;
    __shared__ float s_pr[128], s_bin[128];

    const int t = threadIdx.x;
    const int wid = t >> 5, lid = t & 31;
    const int h = blockIdx.x, b = blockIdx.y;
    const float alpha = __ldg(alpha_p);

    if (t < 128) { s_pr[t] = prior_at(prior, b, h, t); s_bin[t] = b_in[t]; }
    __syncthreads();

    {   // sB <- Win padded (1152 uint4)
        const uint4* src = (const uint4*)g_WinP;
        uint4* dst = (uint4*)sB;
#pragma unroll
        for (int i = 0; i < 5; i++) {
            int idx = t + i * 256;
            if (idx < 1152) dst[idx] = src[idx];
        }
    }
    {   // sA <- F_mod bf16 [c][w]
        const float* xrow = x + (long)b * 1048576 + h * 128;
#pragma unroll
        for (int i = 0; i < 16; i++) {
            int idx = t + i * 256;           // 4096 = 64c x 64 wp
            int c = idx >> 6, wp = idx & 63;
            float2 f = *(const float2*)&xrow[c * 16384 + 2 * wp];
            f.x += alpha * s_pr[2 * wp];
            f.y += alpha * s_pr[2 * wp + 1];
            *(__nv_bfloat162*)&sA[c * LDA1 + 2 * wp] = __float22bfloat162_rn(f);
        }
    }
    __syncthreads();

    // MMA: warp wid owns m-rows w0..w0+15, full N=128, K=64
    const int w0 = wid * 16;
    float acc[16][4];
#pragma unroll
    for (int nt = 0; nt < 16; nt++)
#pragma unroll
        for (int j = 0; j < 4; j++) acc[nt][j] = 0.f;

    const uint32_t sA_u = smem_u32(sA), sB_u = smem_u32(sB);
    const int a_row = (lid & 7) + ((lid >> 4) << 3);
    const int a_col = ((lid >> 3) & 1) << 3;
    const uint32_t a_base = sA_u + (uint32_t)((a_row * LDA1 + w0 + a_col) * 2);
    const int lb = lid & 15;
    const uint32_t b_base = sB_u + (uint32_t)(((lb & 7) * LDB1 + ((lb >> 3) << 3)) * 2);

#pragma unroll
    for (int ks = 0; ks < 4; ks++) {
        uint32_t afr[4];
        ldsm_x4_trans(afr, a_base + (uint32_t)(ks * 16 * LDA1 * 2));
#pragma unroll
        for (int nt = 0; nt < 16; nt++) {
            uint32_t bfr[2];
            ldsm_x2(bfr, b_base + (uint32_t)((nt * 8 * LDB1 + ks * 16) * 2));
            mma_bf16(acc[nt], afr, bfr);
        }
    }
    __syncthreads();   // frags in regs; overlay sPb

    {   // acc (+bias) -> sPb[o][w] bf16
        const int g = lid >> 2, q2 = (lid & 3) * 2;
        const int w = w0 + g;
#pragma unroll
        for (int nt = 0; nt < 16; nt++) {
            int o = nt * 8 + q2;
            sPb[o * LDS1 + w]           = __float2bfloat16(acc[nt][0] + s_bin[o]);
            sPb[(o + 1) * LDS1 + w]     = __float2bfloat16(acc[nt][1] + s_bin[o + 1]);
            sPb[o * LDS1 + w + 8]       = __float2bfloat16(acc[nt][2] + s_bin[o]);
            sPb[(o + 1) * LDS1 + w + 8] = __float2bfloat16(acc[nt][3] + s_bin[o + 1]);
        }
    }
    __syncthreads();

    {   // coalesced x_proj write-out (2048 uint4)
        __nv_bfloat16* xp = g_xp + ((long)b * 128 + h) * 16384;
#pragma unroll
        for (int i = 0; i < 8; i++) {
            int idx = t + i * 256;
            int o = idx >> 4, c8 = idx & 15;
            *(uint4*)&xp[o * 128 + c8 * 8] = *(const uint4*)&sPb[o * LDS1 + c8 * 8];
        }
    }
}

// ---- K2: per-(b,o) plane: h-scan + v-scan + sum, one load one store ----
// smem: sX [128h][136w] bf16 34816B @0 ; sS same @34816. total 69632B.
__global__ __launch_bounds__(256) void k2(const float* __restrict__ Bvec) {
    extern __shared__ __align__(16) char smch[];
    __nv_bfloat16* sX = (__nv_bfloat16*)smch;
    __nv_bfloat16* sS = (__nv_bfloat16*)(smch + 34816);

    const int t = threadIdx.x;
    const int o = blockIdx.x, b = blockIdx.y;
    const float a = g_At[o], bv = __ldg(&Bvec[o]);
    const long gbase = (long)b * 2097152 + o * 128;   // + h*16384 + w

    {   // load plane (2048 uint4)
        const __nv_bfloat16* src = g_xp + gbase;
#pragma unroll
        for (int i = 0; i < 8; i++) {
            int idx = t + i * 256;
            int h = idx >> 4, c8 = idx & 15;
            *(uint4*)&sX[h * LDK2 + c8 * 8] = *(const uint4*)&src[(long)h * 16384 + c8 * 8];
        }
    }
    __syncthreads();

    if (t < 128) {   // h-scan: row h = t, along w; write h_hor into sS
        const __nv_bfloat16* xr = &sX[t * LDK2];
        __nv_bfloat16* sr = &sS[t * LDK2];
        float st = 0.0f;
#pragma unroll 4
        for (int wb = 0; wb < 32; wb++) {
            uint2 u = *(const uint2*)&xr[wb * 4];
            float2 f0 = __bfloat1622float2(*(__nv_bfloat162*)&u.x);
            float2 f1 = __bfloat1622float2(*(__nv_bfloat162*)&u.y);
            st = fmaf(a, st, bv * f0.x); f0.x = st;
            st = fmaf(a, st, bv * f0.y); f0.y = st;
            st = fmaf(a, st, bv * f1.x); f1.x = st;
            st = fmaf(a, st, bv * f1.y); f1.y = st;
            __nv_bfloat162 p0 = __float22bfloat162_rn(f0);
            __nv_bfloat162 p1 = __float22bfloat162_rn(f1);
            *(uint2*)&sr[wb * 4] = make_uint2(*(uint32_t*)&p0, *(uint32_t*)&p1);
        }
    }
    __syncthreads();

    if (t < 128) {   // v-scan: column w = t, along h; sS += v-state
        float st = 0.0f;
#pragma unroll 4
        for (int h = 0; h < 128; h++) {
            float xv = __bfloat162float(sX[h * LDK2 + t]);
            st = fmaf(a, st, bv * xv);
            float sv = __bfloat162float(sS[h * LDK2 + t]) + st;
            sS[h * LDK2 + t] = __float2bfloat16(sv);
        }
    }
    __syncthreads();

    {   // store h_sum plane (2048 uint4)
        __nv_bfloat16* dst = g_hs + gbase;
#pragma unroll
        for (int i = 0; i < 8; i++) {
            int idx = t + i * 256;
            int h = idx >> 4, c8 = idx & 15;
            *(uint4*)&dst[(long)h * 16384 + c8 * 8] = *(const uint4*)&sS[h * LDK2 + c8 * 8];
        }
    }
}

// ---- K3: per-(b,h): out = h_sum @ Wout^T (HMMA), fused epilogue ----
// smem: sA [128o][136w] bf16 34816B @0 ; sB [64c][136o] bf16 17408B @34816
//       sR [64c][132w] f32 33792B overlays sA after MMA.
__global__ __launch_bounds__(256) void k3(
    const float* __restrict__ x, const float* __restrict__ prior,
    const float* __restrict__ b_out, const float* __restrict__ alpha_p,
    const float* __restrict__ gamma_p, float* __restrict__ out)
{
    extern __shared__ __align__(16) char smch[];
    __nv_bfloat16* sA = (__nv_bfloat16*)smch;
    __nv_bfloat16* sB = (__nv_bfloat16*)(smch + 34816);
    float* sR = (float*)smch;
    __shared__ float s_pr[128], s_bo[64];

    const int t = threadIdx.x;
    const int wid = t >> 5, lid = t & 31;
    const int h = blockIdx.x, b = blockIdx.y;
    const float alpha = __ldg(alpha_p), gamma = __ldg(gamma_p);

    if (t < 128) s_pr[t] = prior_at(prior, b, h, t);
    if (t < 64) s_bo[t] = b_out[t];

    {   // sB <- Wout padded (1088 uint4)
        const uint4* src = (const uint4*)g_WoutP;
        uint4* dst = (uint4*)sB;
#pragma unroll
        for (int i = 0; i < 5; i++) {
            int idx = t + i * 256;
            if (idx < 1088) dst[idx] = src[idx];
        }
    }
    {   // sA <- h_sum [o][w]
        const __nv_bfloat16* hs = g_hs + ((long)b * 128 + h) * 16384;
#pragma unroll
        for (int i = 0; i < 8; i++) {
            int idx = t + i * 256;           // 2048 = 128o x 16 w8
            int o = idx >> 4, w8 = idx & 15;
            uint4 v = *(const uint4*)&hs[o * 128 + w8 * 8];
            *(uint4*)&sA[o * LDA3 + w8 * 8] = v;
        }
    }
    __syncthreads();

    // MMA: M=128(w) x N=64(c) x K=128(o)
    const int w0 = wid * 16;
    float acc[8][4];
#pragma unroll
    for (int nt = 0; nt < 8; nt++)
#pragma unroll
        for (int j = 0; j < 4; j++) acc[nt][j] = 0.f;

    const uint32_t sA_u = smem_u32(sA), sB_u = smem_u32(sB);
    const int a_row = (lid & 7) + ((lid >> 4) << 3);
    const int a_col = ((lid >> 3) & 1) << 3;
    const uint32_t a_base = sA_u + (uint32_t)((a_row * LDA3 + w0 + a_col) * 2);
    const int lb = lid & 15;
    const uint32_t b_base = sB_u + (uint32_t)(((lb & 7) * LDB3 + ((lb >> 3) << 3)) * 2);

#pragma unroll
    for (int ks = 0; ks < 8; ks++) {
        uint32_t afr[4];
        ldsm_x4_trans(afr, a_base + (uint32_t)(ks * 16 * LDA3 * 2));
#pragma unroll
        for (int nt = 0; nt < 8; nt++) {
            uint32_t bfr[2];
            ldsm_x2(bfr, b_base + (uint32_t)((nt * 8 * LDB3 + ks * 16) * 2));
            mma_bf16(acc[nt], afr, bfr);
        }
    }
    __syncthreads();   // overlay sR

    {   // acc -> sR[c][w]
        const int g = lid >> 2, q2 = (lid & 3) * 2;
        const int w = w0 + g;
#pragma unroll
        for (int nt = 0; nt < 8; nt++) {
            int c = nt * 8 + q2;
            sR[c * LDP + w]           = acc[nt][0];
            sR[(c + 1) * LDP + w]     = acc[nt][1];
            sR[c * LDP + w + 8]       = acc[nt][2];
            sR[(c + 1) * LDP + w + 8] = acc[nt][3];
        }
    }
    __syncthreads();

    {   // fused epilogue: out = x + alpha*pr + gamma*(res + b_out)
#pragma unroll
        for (int i = 0; i < 32; i++) {
            int idx = t + i * 256;           // 8192 = 64c x 128w
            int c = idx >> 7, w = idx & 127;
            long gb = (((long)b * 64 + c) * 128 + h) * 128 + w;
            float val = sR[c * LDP + w];
            out[gb] = fmaf(alpha, s_pr[w], x[gb]) + gamma * (val + s_bo[c]);
        }
    }
}

extern "C" void kernel_launch(void* const* d_in, const int* in_sizes, int n_in,
                              void* d_out, int out_size) {
    const float* x      = (const float*)d_in[0];
    const float* prior  = (const float*)d_in[1];
    const float* W_in   = (const float*)d_in[2];
    const float* b_in   = (const float*)d_in[3];
    const float* A      = (const float*)d_in[4];
    const float* B      = (const float*)d_in[5];
    const float* alpha  = (const float*)d_in[6];
    const float* gamma  = (const float*)d_in[7];
    const float* W_out  = (const float*)d_in[8];
    const float* b_out  = (const float*)d_in[9];
    float* out = (float*)d_out;

    const int smem_k1 = 35840;
    const int smem_k2 = 69632;
    const int smem_k3 = 34816 + 17408;   // 52224

    cudaFuncSetAttribute(k1, cudaFuncAttributeMaxDynamicSharedMemorySize, smem_k1);
    cudaFuncSetAttribute(k2, cudaFuncAttributeMaxDynamicSharedMemorySize, smem_k2);
    cudaFuncSetAttribute(k3, cudaFuncAttributeMaxDynamicSharedMemorySize, smem_k3);

    k_setup<<<32, 256>>>(W_in, W_out, A);
    dim3 grid(HDIM, BSZ);
    k1<<<grid, 256, smem_k1>>>(x, prior, b_in, alpha);
    k2<<<grid, 256, smem_k2>>>(B);
    k3<<<grid, 256, smem_k3>>>(x, prior, b_out, alpha, gamma, out);
}